// round 4
// baseline (speedup 1.0000x reference)
#include <cuda_runtime.h>
#include <math.h>

#define FULL 0xffffffffu

// ---------------- scratch (no cudaMalloc allowed) ----------------
__device__ float g_xmicro[8192 * 256];   // [B*Nd, 256]
__device__ float g_Q[8192 * 256];        // [B*Nd, 256]
__device__ float g_K[32768 * 256];       // [B*Nc, 256]
__device__ float g_V[32768 * 256];       // [B*Nc, 256]
__device__ float g_ctx[8192 * 256];      // [B*Nd, 256]

// ---------------- kernel 1: x_micro = micro @ mp_w + mp_b ----------------
__global__ void micro_proj_kernel(const float* __restrict__ micro,
                                  const float* __restrict__ mp_w,
                                  const float* __restrict__ mp_b,
                                  float* __restrict__ xm) {
    int row = blockIdx.x;          // 0..8191
    int j = threadIdx.x;           // 0..255
    const float* mrow = micro + row * 11;
    float acc = mp_b[j];
#pragma unroll
    for (int i = 0; i < 11; ++i) acc += mrow[i] * mp_w[i * 256 + j];
    xm[row * 256 + j] = acc;
}

// ---------------- kernel 2: C[M,256] = A[M,256] @ W[256,256] (+bias)(+res) ----
// BM=128, BN=128, BK=16, 256 threads, 8x8 micro-tile. M multiple of 128.
__global__ __launch_bounds__(256, 2)
void gemm256_kernel(const float* __restrict__ A, const float* __restrict__ W,
                    const float* __restrict__ bias, const float* __restrict__ res,
                    float* __restrict__ C) {
    __shared__ float As[16 * 132];   // A transposed: As[k][m]
    __shared__ float Bs[16 * 132];   // Bs[k][n]

    int tid = threadIdx.x;
    int m0 = blockIdx.x * 128;
    int n0 = blockIdx.y * 128;
    int ng = tid & 15;      // n group (8 cols)
    int mg = tid >> 4;      // m group (8 rows)

    float acc[8][8];
#pragma unroll
    for (int i = 0; i < 8; ++i)
#pragma unroll
        for (int j = 0; j < 8; ++j) acc[i][j] = 0.f;

    int ar = tid >> 2, akq = tid & 3;     // A staging: 64 rows/pass, float4 along k
    int bn = (tid & 31) * 4, bk = tid >> 5;  // B staging

    for (int kb = 0; kb < 16; ++kb) {
        __syncthreads();
#pragma unroll
        for (int p = 0; p < 2; ++p) {
            int m = ar + p * 64;
            float4 av = *(const float4*)&A[(size_t)(m0 + m) * 256 + kb * 16 + akq * 4];
            As[(akq * 4 + 0) * 132 + m] = av.x;
            As[(akq * 4 + 1) * 132 + m] = av.y;
            As[(akq * 4 + 2) * 132 + m] = av.z;
            As[(akq * 4 + 3) * 132 + m] = av.w;
        }
#pragma unroll
        for (int p = 0; p < 2; ++p) {
            int k = bk + p * 8;
            *(float4*)&Bs[k * 132 + bn] =
                *(const float4*)&W[(size_t)(kb * 16 + k) * 256 + n0 + bn];
        }
        __syncthreads();
#pragma unroll
        for (int k = 0; k < 16; ++k) {
            float a[8], b[8];
            *(float4*)&a[0] = *(float4*)&As[k * 132 + 8 * mg];
            *(float4*)&a[4] = *(float4*)&As[k * 132 + 8 * mg + 4];
            *(float4*)&b[0] = *(float4*)&Bs[k * 132 + 8 * ng];
            *(float4*)&b[4] = *(float4*)&Bs[k * 132 + 8 * ng + 4];
#pragma unroll
            for (int i = 0; i < 8; ++i)
#pragma unroll
                for (int j = 0; j < 8; ++j) acc[i][j] += a[i] * b[j];
        }
    }

#pragma unroll
    for (int i = 0; i < 8; ++i) {
        int r = m0 + 8 * mg + i;
        int c = n0 + 8 * ng;
        float v[8];
#pragma unroll
        for (int j = 0; j < 8; ++j) {
            v[j] = acc[i][j];
            if (bias) v[j] += bias[c + j];
            if (res)  v[j] += res[(size_t)r * 256 + c + j];
        }
        *(float4*)&C[(size_t)r * 256 + c]     = *(float4*)&v[0];
        *(float4*)&C[(size_t)r * 256 + c + 4] = *(float4*)&v[4];
    }
}

// ---------------- kernel 3: scores + streaming top-32 + softmax + context ----
// Grid: B * (2048/32) = 256 CTAs. 256 threads. 32 queries x 8192 cells each.
// Per-warp top-32 lists held sorted in registers (lane = rank), warp-shuffle
// insertion. Chunk = 128 cells, scores via smem-tiled fp32 GEMM.
__global__ __launch_bounds__(256, 2)
void attn_topk_kernel(const float* __restrict__ Qb, const float* __restrict__ Kf,
                      const float* __restrict__ Vf, float* __restrict__ ctx,
                      float* __restrict__ out_attn, float* __restrict__ out_idx) {
    extern __shared__ float sm[];
    float* Qs = sm;                  // [256][36]  query tile, transposed
    float* Ks = sm + 256 * 36;       // [32][132]  K d-slab, transposed
    float* Ss = Ks + 32 * 132;       // [32][132]  score chunk

    int tid = threadIdx.x;
    int lane = tid & 31, warp = tid >> 5;
    int b = blockIdx.x >> 6;         // batch
    int qtile = blockIdx.x & 63;     // query tile within batch
    const float* Qg = Qb + ((size_t)b * 2048 + qtile * 32) * 256;
    const float* Kg = Kf + (size_t)b * 8192 * 256;
    const float* Vg = Vf + (size_t)b * 8192 * 256;

    // load Q tile transposed: Qs[d][q]
    for (int i = tid; i < 32 * 256; i += 256) {
        int q = i >> 8, d = i & 255;
        Qs[d * 36 + q] = Qg[i];      // Qg[q*256 + d], coalesced along d
    }

    // per-warp top-32 state: lane l holds rank-l (value desc; stable ties)
    float lval[4], thr[4];
    int lidx[4];
#pragma unroll
    for (int s = 0; s < 4; ++s) { lval[s] = -INFINITY; thr[s] = -INFINITY; lidx[s] = 0; }

    int cg = lane;           // cell group (4 cells)
    int qg = warp;           // query group (4 queries)
    int sd = tid & 31, sc = tid >> 5;   // K staging coords

    for (int chunk = 0; chunk < 64; ++chunk) {
        int cb = chunk * 128;
        float acc[4][4];
#pragma unroll
        for (int i = 0; i < 4; ++i)
#pragma unroll
            for (int j = 0; j < 4; ++j) acc[i][j] = 0.f;

        for (int db = 0; db < 8; ++db) {
            __syncthreads();
            const float* kp = Kg + (size_t)(cb + sc) * 256 + db * 32 + sd;
#pragma unroll
            for (int p = 0; p < 16; ++p)
                Ks[sd * 132 + sc + p * 8] = kp[(size_t)p * 8 * 256];
            __syncthreads();
#pragma unroll
            for (int dd = 0; dd < 32; ++dd) {
                float4 qv = *(const float4*)&Qs[(db * 32 + dd) * 36 + 4 * qg];
                float4 kv = *(const float4*)&Ks[dd * 132 + 4 * cg];
                float qa[4] = {qv.x, qv.y, qv.z, qv.w};
                float ka[4] = {kv.x, kv.y, kv.z, kv.w};
#pragma unroll
                for (int i = 0; i < 4; ++i)
#pragma unroll
                    for (int j = 0; j < 4; ++j) acc[i][j] += qa[i] * ka[j];
            }
        }
        __syncthreads();
        // write scaled scores (scale = 256^-0.5 = 1/16, applied post-sum as in ref)
#pragma unroll
        for (int i = 0; i < 4; ++i) {
            float4 v = make_float4(acc[i][0] * 0.0625f, acc[i][1] * 0.0625f,
                                   acc[i][2] * 0.0625f, acc[i][3] * 0.0625f);
            *(float4*)&Ss[(4 * qg + i) * 132 + 4 * cg] = v;
        }
        __syncthreads();

        // top-k update: warp w owns queries 4w..4w+3
#pragma unroll
        for (int sub = 0; sub < 4; ++sub) {
            int q = 4 * warp + sub;
#pragma unroll
            for (int r = 0; r < 4; ++r) {
                float s = Ss[q * 132 + r * 32 + lane];
                unsigned cand = __ballot_sync(FULL, s > thr[sub]);
                while (cand) {
                    int src = __ffs(cand) - 1;   // lowest index first => stable order
                    cand &= cand - 1;
                    float v = __shfl_sync(FULL, s, src);
                    if (v > thr[sub]) {          // uniform re-check vs. risen threshold
                        // insertion position: existing >= candidate stay above (JAX tie rule)
                        unsigned ge = __ballot_sync(FULL, lval[sub] >= v);
                        int p = __popc(ge);
                        float vu = __shfl_up_sync(FULL, lval[sub], 1);
                        int iu  = __shfl_up_sync(FULL, lidx[sub], 1);
                        if (lane > p)        { lval[sub] = vu; lidx[sub] = iu; }
                        else if (lane == p)  { lval[sub] = v;  lidx[sub] = cb + r * 32 + src; }
                        thr[sub] = __shfl_sync(FULL, lval[sub], 31);
                    }
                }
            }
        }
    }

    // finalize: softmax over 32 (sorted desc), outputs, context = sum w_k * V[idx_k]
#pragma unroll
    for (int sub = 0; sub < 4; ++sub) {
        size_t row = (size_t)b * 2048 + qtile * 32 + 4 * warp + sub;
        float v = lval[sub];
        float m = __shfl_sync(FULL, v, 0);       // rank-0 = max
        float e = expf(v - m);
        float ssum = e;
#pragma unroll
        for (int o = 16; o; o >>= 1) ssum += __shfl_xor_sync(FULL, ssum, o);
        float w = e / ssum;
        out_attn[row * 32 + lane] = w;
        out_idx[row * 32 + lane] = (float)lidx[sub];

        float c[8];
#pragma unroll
        for (int j = 0; j < 8; ++j) c[j] = 0.f;
#pragma unroll
        for (int k = 0; k < 32; ++k) {
            float wk = __shfl_sync(FULL, w, k);
            int cell = __shfl_sync(FULL, lidx[sub], k);
            const float* vr = Vg + (size_t)cell * 256 + lane * 8;
            float4 va = *(const float4*)vr;
            float4 vb = *(const float4*)(vr + 4);
            c[0] += wk * va.x; c[1] += wk * va.y; c[2] += wk * va.z; c[3] += wk * va.w;
            c[4] += wk * vb.x; c[5] += wk * vb.y; c[6] += wk * vb.z; c[7] += wk * vb.w;
        }
        float* cp = ctx + row * 256 + lane * 8;
        *(float4*)cp       = make_float4(c[0], c[1], c[2], c[3]);
        *(float4*)(cp + 4) = make_float4(c[4], c[5], c[6], c[7]);
    }
}

// ---------------- launch ----------------
extern "C" void kernel_launch(void* const* d_in, const int* in_sizes, int n_in,
                              void* d_out, int out_size) {
    const float* micro = (const float*)d_in[0];   // [4,2048,11]
    const float* macro = (const float*)d_in[1];   // [4,8192,256]
    const float* mp_w  = (const float*)d_in[2];   // [11,256]
    const float* mp_b  = (const float*)d_in[3];   // [256]
    const float* wq    = (const float*)d_in[4];   // [256,256]
    const float* wk    = (const float*)d_in[5];
    const float* wv    = (const float*)d_in[6];
    const float* op_w  = (const float*)d_in[7];
    const float* op_b  = (const float*)d_in[8];
    float* out = (float*)d_out;   // [x_cond 2097152 | attn 262144 | idx 262144]

    float *xm, *Qb, *Kf, *Vf, *ctx;
    cudaGetSymbolAddress((void**)&xm,  g_xmicro);
    cudaGetSymbolAddress((void**)&Qb,  g_Q);
    cudaGetSymbolAddress((void**)&Kf,  g_K);
    cudaGetSymbolAddress((void**)&Vf,  g_V);
    cudaGetSymbolAddress((void**)&ctx, g_ctx);

    micro_proj_kernel<<<8192, 256>>>(micro, mp_w, mp_b, xm);
    gemm256_kernel<<<dim3(64, 2), 256>>>(xm, wq, nullptr, nullptr, Qb);        // Q
    gemm256_kernel<<<dim3(256, 2), 256>>>(macro, wk, nullptr, nullptr, Kf);    // K_full
    gemm256_kernel<<<dim3(256, 2), 256>>>(macro, wv, nullptr, nullptr, Vf);    // V_full

    int smem = (256 * 36 + 32 * 132 + 32 * 132) * 4;   // 70656 B
    cudaFuncSetAttribute(attn_topk_kernel,
                         cudaFuncAttributeMaxDynamicSharedMemorySize, smem);
    attn_topk_kernel<<<256, 256, smem>>>(Qb, Kf, Vf, ctx,
                                         out + 8192 * 256,
                                         out + 8192 * 256 + 8192 * 32);

    // x_cond = x_micro + ctx @ op_w + op_b
    gemm256_kernel<<<dim3(64, 2), 256>>>(ctx, op_w, op_b, xm, out);
}

// round 10
// speedup vs baseline: 1.3668x; 1.3668x over previous
#include <cuda_runtime.h>
#include <math.h>

#define FULL 0xffffffffu

// ---------------- scratch (no cudaMalloc allowed) ----------------
__device__ float g_xmicro[8192 * 256];   // [B*Nd, 256]
__device__ float g_Q[8192 * 256];        // [B*Nd, 256]
__device__ float g_K[32768 * 256];       // [B*Nc, 256]
__device__ float g_V[32768 * 256];       // [B*Nc, 256]
__device__ float g_ctx[8192 * 256];      // [B*Nd, 256]

// ---------------- kernel 1: x_micro = micro @ mp_w + mp_b ----------------
__global__ void micro_proj_kernel(const float* __restrict__ micro,
                                  const float* __restrict__ mp_w,
                                  const float* __restrict__ mp_b,
                                  float* __restrict__ xm) {
    int row = blockIdx.x;
    int j = threadIdx.x;
    const float* mrow = micro + row * 11;
    float acc = mp_b[j];
#pragma unroll
    for (int i = 0; i < 11; ++i) acc += mrow[i] * mp_w[i * 256 + j];
    xm[row * 256 + j] = acc;
}

// ---------------- kernel 2: C[M,256] = A[M,256] @ W[256,256] (+bias)(+res) ----
__global__ __launch_bounds__(256, 2)
void gemm256_kernel(const float* __restrict__ A, const float* __restrict__ W,
                    const float* __restrict__ bias, const float* __restrict__ res,
                    float* __restrict__ C) {
    __shared__ float As[16 * 132];
    __shared__ float Bs[16 * 132];

    int tid = threadIdx.x;
    int m0 = blockIdx.x * 128;
    int n0 = blockIdx.y * 128;
    int ng = tid & 15;
    int mg = tid >> 4;

    float acc[8][8];
#pragma unroll
    for (int i = 0; i < 8; ++i)
#pragma unroll
        for (int j = 0; j < 8; ++j) acc[i][j] = 0.f;

    int ar = tid >> 2, akq = tid & 3;
    int bn = (tid & 31) * 4, bk = tid >> 5;

    for (int kb = 0; kb < 16; ++kb) {
        __syncthreads();
#pragma unroll
        for (int p = 0; p < 2; ++p) {
            int m = ar + p * 64;
            float4 av = *(const float4*)&A[(size_t)(m0 + m) * 256 + kb * 16 + akq * 4];
            As[(akq * 4 + 0) * 132 + m] = av.x;
            As[(akq * 4 + 1) * 132 + m] = av.y;
            As[(akq * 4 + 2) * 132 + m] = av.z;
            As[(akq * 4 + 3) * 132 + m] = av.w;
        }
#pragma unroll
        for (int p = 0; p < 2; ++p) {
            int k = bk + p * 8;
            *(float4*)&Bs[k * 132 + bn] =
                *(const float4*)&W[(size_t)(kb * 16 + k) * 256 + n0 + bn];
        }
        __syncthreads();
#pragma unroll
        for (int k = 0; k < 16; ++k) {
            float a[8], b[8];
            *(float4*)&a[0] = *(float4*)&As[k * 132 + 8 * mg];
            *(float4*)&a[4] = *(float4*)&As[k * 132 + 8 * mg + 4];
            *(float4*)&b[0] = *(float4*)&Bs[k * 132 + 8 * ng];
            *(float4*)&b[4] = *(float4*)&Bs[k * 132 + 8 * ng + 4];
#pragma unroll
            for (int i = 0; i < 8; ++i)
#pragma unroll
                for (int j = 0; j < 8; ++j) acc[i][j] += a[i] * b[j];
        }
    }

#pragma unroll
    for (int i = 0; i < 8; ++i) {
        int r = m0 + 8 * mg + i;
        int c = n0 + 8 * ng;
        float v[8];
#pragma unroll
        for (int j = 0; j < 8; ++j) {
            v[j] = acc[i][j];
            if (bias) v[j] += bias[c + j];
            if (res)  v[j] += res[(size_t)r * 256 + c + j];
        }
        *(float4*)&C[(size_t)r * 256 + c]     = *(float4*)&v[0];
        *(float4*)&C[(size_t)r * 256 + c + 4] = *(float4*)&v[4];
    }
}

// ---------------- tf32 helpers ----------------
__device__ __forceinline__ float to_tf32(float x) {
    unsigned r;
    asm("cvt.rna.tf32.f32 %0, %1;" : "=r"(r) : "f"(x));
    return __uint_as_float(r);
}

__device__ __forceinline__ void mma_tf32(float* d, const unsigned* a,
                                         unsigned b0, unsigned b1) {
    asm volatile(
        "mma.sync.aligned.m16n8k8.row.col.f32.tf32.tf32.f32 "
        "{%0,%1,%2,%3}, {%4,%5,%6,%7}, {%8,%9}, {%0,%1,%2,%3};"
        : "+f"(d[0]), "+f"(d[1]), "+f"(d[2]), "+f"(d[3])
        : "r"(a[0]), "r"(a[1]), "r"(a[2]), "r"(a[3]), "r"(b0), "r"(b1));
}

// ---------------- kernel 3: tf32-mma scores + top-64 preselect +
//   exact fp32 rescore (sequential ascending-k chains, matching the
//   round-4 passing kernel's summation order bitwise) + exact top-32 +
//   softmax + context ----------
__global__ __launch_bounds__(256, 2)
void attn_topk_kernel(const float* __restrict__ Qb, const float* __restrict__ Kf,
                      const float* __restrict__ Vf, float* __restrict__ ctx,
                      float* __restrict__ out_attn, float* __restrict__ out_idx) {
    extern __shared__ float sm[];
    float* Qs = sm;                   // [32][260] tf32-rounded Q
    float* Ks = sm + 32 * 260;        // [256][36] tf32-rounded K d-slab
    float* Ss = Ks + 256 * 36;        // [32][260] approx scores (scaled)
    const unsigned* Qsu = (const unsigned*)Qs;
    const unsigned* Ksu = (const unsigned*)Ks;

    int tid = threadIdx.x;
    int lane = tid & 31, warp = tid >> 5;
    int g = lane >> 2, t = lane & 3;
    int b = blockIdx.x >> 6;
    int qtile = blockIdx.x & 63;
    const float* Qg = Qb + ((size_t)b * 2048 + qtile * 32) * 256;
    const float* Kg = Kf + (size_t)b * 8192 * 256;
    const float* Vg = Vf + (size_t)b * 8192 * 256;

    // stage Q tile (tf32-rounded) once
    for (int i = tid; i < 32 * 256; i += 256) {
        int q = i >> 8, d = i & 255;
        Qs[q * 260 + d] = to_tf32(Qg[i]);
    }

    // approx top-64 per query: lane l holds ranks l (v0/i0) and 32+l (v1/i1)
    float v0[4], v1[4], thr[4];
    int i0[4], i1[4];
#pragma unroll
    for (int s = 0; s < 4; ++s) {
        v0[s] = -INFINITY; v1[s] = -INFINITY; thr[s] = -INFINITY;
        i0[s] = 0; i1[s] = 0;
    }

    int nb = 32 * warp;   // this warp's cell base within the chunk

    for (int chunk = 0; chunk < 32; ++chunk) {
        int cb = chunk * 256;
        float d[2][4][4];
#pragma unroll
        for (int mt = 0; mt < 2; ++mt)
#pragma unroll
            for (int ns = 0; ns < 4; ++ns)
#pragma unroll
                for (int r = 0; r < 4; ++r) d[mt][ns][r] = 0.f;

        for (int slab = 0; slab < 8; ++slab) {
            int kb = slab * 32;
            __syncthreads();
            // stage K slab: 256 cells x 32 dims (tf32-rounded)
#pragma unroll
            for (int p = 0; p < 8; ++p) {
                int c = p * 32 + (tid >> 3);
                int dp = tid & 7;
                float4 kv = *(const float4*)&Kg[(size_t)(cb + c) * 256 + kb + dp * 4];
                float4 o = make_float4(to_tf32(kv.x), to_tf32(kv.y),
                                       to_tf32(kv.z), to_tf32(kv.w));
                *(float4*)&Ks[c * 36 + dp * 4] = o;
            }
            __syncthreads();
#pragma unroll
            for (int kt = 0; kt < 4; ++kt) {
                int kc = kb + kt * 8;     // column in Qs
                int kl = kt * 8;          // column in Ks
                unsigned a[2][4];
#pragma unroll
                for (int mt = 0; mt < 2; ++mt) {
                    const unsigned* qr = Qsu + (16 * mt + g) * 260 + kc + t;
                    a[mt][0] = qr[0];
                    a[mt][1] = qr[8 * 260];
                    a[mt][2] = qr[4];
                    a[mt][3] = qr[8 * 260 + 4];
                }
#pragma unroll
                for (int ns = 0; ns < 4; ++ns) {
                    unsigned b0 = Ksu[(nb + 8 * ns + g) * 36 + kl + t];
                    unsigned b1 = Ksu[(nb + 8 * ns + g) * 36 + kl + t + 4];
                    mma_tf32(&d[0][ns][0], a[0], b0, b1);
                    mma_tf32(&d[1][ns][0], a[1], b0, b1);
                }
            }
        }

        // epilogue: accumulators -> Ss (scaled by 1/16)
#pragma unroll
        for (int mt = 0; mt < 2; ++mt)
#pragma unroll
            for (int ns = 0; ns < 4; ++ns) {
                int row = 16 * mt + g;
                int col = nb + 8 * ns + 2 * t;
                *(float2*)&Ss[row * 260 + col] =
                    make_float2(d[mt][ns][0] * 0.0625f, d[mt][ns][1] * 0.0625f);
                *(float2*)&Ss[(row + 8) * 260 + col] =
                    make_float2(d[mt][ns][2] * 0.0625f, d[mt][ns][3] * 0.0625f);
            }
        __syncthreads();

        // streaming approx top-64: warp w owns queries 4w..4w+3
#pragma unroll
        for (int sub = 0; sub < 4; ++sub) {
            int q = 4 * warp + sub;
#pragma unroll
            for (int r = 0; r < 8; ++r) {
                float s = Ss[q * 260 + r * 32 + lane];
                unsigned candm = __ballot_sync(FULL, s > thr[sub]);
                while (candm) {
                    int src = __ffs(candm) - 1;
                    candm &= candm - 1;
                    float v = __shfl_sync(FULL, s, src);
                    if (v > thr[sub]) {
                        int nidx = cb + r * 32 + src;
                        unsigned ge0 = __ballot_sync(FULL, v0[sub] >= v);
                        unsigned ge1 = __ballot_sync(FULL, v1[sub] >= v);
                        int p = __popc(ge0) + __popc(ge1);
                        float b31v = __shfl_sync(FULL, v0[sub], 31);
                        int   b31i = __shfl_sync(FULL, i0[sub], 31);
                        float v0u = __shfl_up_sync(FULL, v0[sub], 1);
                        int   i0u = __shfl_up_sync(FULL, i0[sub], 1);
                        float v1u = __shfl_up_sync(FULL, v1[sub], 1);
                        int   i1u = __shfl_up_sync(FULL, i1[sub], 1);
                        if (p < 32) {
                            if (lane > p)       { v0[sub] = v0u; i0[sub] = i0u; }
                            else if (lane == p) { v0[sub] = v;   i0[sub] = nidx; }
                            v1[sub] = (lane == 0) ? b31v : v1u;
                            i1[sub] = (lane == 0) ? b31i : i1u;
                        } else {
                            int pq = p - 32;
                            if (lane > pq)       { v1[sub] = v1u; i1[sub] = i1u; }
                            else if (lane == pq) { v1[sub] = v;   i1[sub] = nidx; }
                        }
                        thr[sub] = __shfl_sync(FULL, v1[sub], 31);
                    }
                }
            }
        }
    }

    // ---- exact fp32 rescore of 64 candidates (each lane owns 2 candidates,
    //      sequential ascending-k FFMA chain == reference-correlated order),
    //      then exact top-32 via strict total order + softmax + context ----
#pragma unroll
    for (int sub = 0; sub < 4; ++sub) {
        size_t row = (size_t)b * 2048 + qtile * 32 + 4 * warp + sub;
        const float* Qrow = Qg + (4 * warp + sub) * 256;
        const float* k0p = Kg + (size_t)i0[sub] * 256;
        const float* k1p = Kg + (size_t)i1[sub] * 256;

        float s0 = 0.f, s1 = 0.f;
#pragma unroll 8
        for (int dq = 0; dq < 64; ++dq) {
            float4 q4 = *(const float4*)&Qrow[4 * dq];   // broadcast across lanes
            float4 a4 = *(const float4*)&k0p[4 * dq];
            float4 b4 = *(const float4*)&k1p[4 * dq];
            s0 = fmaf(q4.x, a4.x, s0); s0 = fmaf(q4.y, a4.y, s0);
            s0 = fmaf(q4.z, a4.z, s0); s0 = fmaf(q4.w, a4.w, s0);
            s1 = fmaf(q4.x, b4.x, s1); s1 = fmaf(q4.y, b4.y, s1);
            s1 = fmaf(q4.z, b4.z, s1); s1 = fmaf(q4.w, b4.w, s1);
        }
        s0 *= 0.0625f;
        s1 *= 0.0625f;

        // exact top-32 among 64 candidates. Comparator (value desc, idx asc)
        // is a strict total order (indices distinct), so the result is
        // independent of insertion order and matches JAX top_k tie rules.
        float ev = -INFINITY;
        int ei = 0x7fffffff;
        for (int k = 0; k < 64; ++k) {
            float v  = (k < 32) ? __shfl_sync(FULL, s0, k)
                                : __shfl_sync(FULL, s1, k - 32);
            int cell = (k < 32) ? __shfl_sync(FULL, i0[sub], k)
                                : __shfl_sync(FULL, i1[sub], k - 32);
            unsigned ge = __ballot_sync(FULL, ev > v || (ev == v && ei < cell));
            int p = __popc(ge);
            float evu = __shfl_up_sync(FULL, ev, 1);
            int   eiu = __shfl_up_sync(FULL, ei, 1);
            if (lane > p)       { ev = evu; ei = eiu; }
            else if (lane == p) { ev = v;   ei = cell; }
        }

        // softmax over sorted-desc exact top-32
        float m = __shfl_sync(FULL, ev, 0);
        float e = expf(ev - m);
        float ssum = e;
#pragma unroll
        for (int o = 16; o; o >>= 1) ssum += __shfl_xor_sync(FULL, ssum, o);
        float w = e / ssum;
        out_attn[row * 32 + lane] = w;
        out_idx[row * 32 + lane] = (float)ei;

        // context = sum_k w_k * V[idx_k]
        float c[8];
#pragma unroll
        for (int j = 0; j < 8; ++j) c[j] = 0.f;
#pragma unroll
        for (int k = 0; k < 32; ++k) {
            float wk = __shfl_sync(FULL, w, k);
            int cell = __shfl_sync(FULL, ei, k);
            const float* vr = Vg + (size_t)cell * 256 + lane * 8;
            float4 va = *(const float4*)vr;
            float4 vb = *(const float4*)(vr + 4);
            c[0] += wk * va.x; c[1] += wk * va.y; c[2] += wk * va.z; c[3] += wk * va.w;
            c[4] += wk * vb.x; c[5] += wk * vb.y; c[6] += wk * vb.z; c[7] += wk * vb.w;
        }
        float* cp = ctx + row * 256 + lane * 8;
        *(float4*)cp       = make_float4(c[0], c[1], c[2], c[3]);
        *(float4*)(cp + 4) = make_float4(c[4], c[5], c[6], c[7]);
    }
}

// ---------------- launch ----------------
extern "C" void kernel_launch(void* const* d_in, const int* in_sizes, int n_in,
                              void* d_out, int out_size) {
    const float* micro = (const float*)d_in[0];
    const float* macro = (const float*)d_in[1];
    const float* mp_w  = (const float*)d_in[2];
    const float* mp_b  = (const float*)d_in[3];
    const float* wq    = (const float*)d_in[4];
    const float* wk    = (const float*)d_in[5];
    const float* wv    = (const float*)d_in[6];
    const float* op_w  = (const float*)d_in[7];
    const float* op_b  = (const float*)d_in[8];
    float* out = (float*)d_out;

    float *xm, *Qb, *Kf, *Vf, *ctx;
    cudaGetSymbolAddress((void**)&xm,  g_xmicro);
    cudaGetSymbolAddress((void**)&Qb,  g_Q);
    cudaGetSymbolAddress((void**)&Kf,  g_K);
    cudaGetSymbolAddress((void**)&Vf,  g_V);
    cudaGetSymbolAddress((void**)&ctx, g_ctx);

    micro_proj_kernel<<<8192, 256>>>(micro, mp_w, mp_b, xm);
    gemm256_kernel<<<dim3(64, 2), 256>>>(xm, wq, nullptr, nullptr, Qb);
    gemm256_kernel<<<dim3(256, 2), 256>>>(macro, wk, nullptr, nullptr, Kf);
    gemm256_kernel<<<dim3(256, 2), 256>>>(macro, wv, nullptr, nullptr, Vf);

    int smem = (32 * 260 + 256 * 36 + 32 * 260) * 4;   // 103424 B
    cudaFuncSetAttribute(attn_topk_kernel,
                         cudaFuncAttributeMaxDynamicSharedMemorySize, smem);
    attn_topk_kernel<<<256, 256, smem>>>(Qb, Kf, Vf, ctx,
                                         out + 8192 * 256,
                                         out + 8192 * 256 + 8192 * 32);

    gemm256_kernel<<<dim3(64, 2), 256>>>(ctx, op_w, op_b, xm, out);
}

// round 12
// speedup vs baseline: 1.7430x; 1.2752x over previous
#include <cuda_runtime.h>
#include <cuda_bf16.h>
#include <math.h>

#define FULL 0xffffffffu

// ---------------- scratch (no cudaMalloc allowed) ----------------
__device__ float g_xmicro[8192 * 256];           // [B*Nd, 256]
__device__ float g_Q[8192 * 256];                // [B*Nd, 256]
__device__ float g_K[32768 * 256];               // [B*Nc, 256]
__device__ float g_V[32768 * 256];               // [B*Nc, 256]
__device__ float g_ctx[8192 * 256];              // [B*Nd, 256]
__device__ __nv_bfloat16 g_Kbf[32768 * 256];     // bf16 copy of K for preselect

// ---------------- kernel 1: x_micro = micro @ mp_w + mp_b ----------------
__global__ void micro_proj_kernel(const float* __restrict__ micro,
                                  const float* __restrict__ mp_w,
                                  const float* __restrict__ mp_b,
                                  float* __restrict__ xm) {
    int row = blockIdx.x;
    int j = threadIdx.x;
    const float* mrow = micro + row * 11;
    float acc = mp_b[j];
#pragma unroll
    for (int i = 0; i < 11; ++i) acc += mrow[i] * mp_w[i * 256 + j];
    xm[row * 256 + j] = acc;
}

// ---------------- kernel 2: C[M,256] = A[M,256] @ W[256,256] (+bias)(+res) ----
// Optionally also emits a bf16 copy of C (for the preselect path).
__global__ __launch_bounds__(256, 2)
void gemm256_kernel(const float* __restrict__ A, const float* __restrict__ W,
                    const float* __restrict__ bias, const float* __restrict__ res,
                    float* __restrict__ C, __nv_bfloat16* __restrict__ Cbf) {
    __shared__ float As[16 * 132];
    __shared__ float Bs[16 * 132];

    int tid = threadIdx.x;
    int m0 = blockIdx.x * 128;
    int n0 = blockIdx.y * 128;
    int ng = tid & 15;
    int mg = tid >> 4;

    float acc[8][8];
#pragma unroll
    for (int i = 0; i < 8; ++i)
#pragma unroll
        for (int j = 0; j < 8; ++j) acc[i][j] = 0.f;

    int ar = tid >> 2, akq = tid & 3;
    int bn = (tid & 31) * 4, bk = tid >> 5;

    for (int kb = 0; kb < 16; ++kb) {
        __syncthreads();
#pragma unroll
        for (int p = 0; p < 2; ++p) {
            int m = ar + p * 64;
            float4 av = *(const float4*)&A[(size_t)(m0 + m) * 256 + kb * 16 + akq * 4];
            As[(akq * 4 + 0) * 132 + m] = av.x;
            As[(akq * 4 + 1) * 132 + m] = av.y;
            As[(akq * 4 + 2) * 132 + m] = av.z;
            As[(akq * 4 + 3) * 132 + m] = av.w;
        }
#pragma unroll
        for (int p = 0; p < 2; ++p) {
            int k = bk + p * 8;
            *(float4*)&Bs[k * 132 + bn] =
                *(const float4*)&W[(size_t)(kb * 16 + k) * 256 + n0 + bn];
        }
        __syncthreads();
#pragma unroll
        for (int k = 0; k < 16; ++k) {
            float a[8], b[8];
            *(float4*)&a[0] = *(float4*)&As[k * 132 + 8 * mg];
            *(float4*)&a[4] = *(float4*)&As[k * 132 + 8 * mg + 4];
            *(float4*)&b[0] = *(float4*)&Bs[k * 132 + 8 * ng];
            *(float4*)&b[4] = *(float4*)&Bs[k * 132 + 8 * ng + 4];
#pragma unroll
            for (int i = 0; i < 8; ++i)
#pragma unroll
                for (int j = 0; j < 8; ++j) acc[i][j] += a[i] * b[j];
        }
    }

#pragma unroll
    for (int i = 0; i < 8; ++i) {
        int r = m0 + 8 * mg + i;
        int c = n0 + 8 * ng;
        float v[8];
#pragma unroll
        for (int j = 0; j < 8; ++j) {
            v[j] = acc[i][j];
            if (bias) v[j] += bias[c + j];
            if (res)  v[j] += res[(size_t)r * 256 + c + j];
        }
        *(float4*)&C[(size_t)r * 256 + c]     = *(float4*)&v[0];
        *(float4*)&C[(size_t)r * 256 + c + 4] = *(float4*)&v[4];
        if (Cbf) {
            __nv_bfloat16 h[8];
#pragma unroll
            for (int j = 0; j < 8; ++j) h[j] = __float2bfloat16(v[j]);
            *(float4*)&Cbf[(size_t)r * 256 + c] = *(const float4*)h;
        }
    }
}

// ---------------- bf16 mma helper ----------------
__device__ __forceinline__ void mma_bf16(float* d, const unsigned* a,
                                         unsigned b0, unsigned b1) {
    asm volatile(
        "mma.sync.aligned.m16n8k16.row.col.f32.bf16.bf16.f32 "
        "{%0,%1,%2,%3}, {%4,%5,%6,%7}, {%8,%9}, {%0,%1,%2,%3};"
        : "+f"(d[0]), "+f"(d[1]), "+f"(d[2]), "+f"(d[3])
        : "r"(a[0]), "r"(a[1]), "r"(a[2]), "r"(a[3]), "r"(b0), "r"(b1));
}

// ---------------- kernel 3: bf16-mma approx scores + top-64 preselect +
//   exact fp32 rescore (sequential ascending-k chains; reference-correlated)
//   + exact top-32 + softmax + context ----------
// Grid: 256 CTAs (4 batches x 64 query tiles of 32). 256 threads.
// Chunk = 256 cells; K staged in bf16 d-slabs of 64. Warp w: 2 m-tiles,
// n-tiles 4w..4w+3 (cells 32w..32w+31 of the chunk).
__global__ __launch_bounds__(256, 2)
void attn_topk_kernel(const float* __restrict__ Qb,
                      const float* __restrict__ Kf,
                      const __nv_bfloat16* __restrict__ Kbf,
                      const float* __restrict__ Vf, float* __restrict__ ctx,
                      float* __restrict__ out_attn, float* __restrict__ out_idx) {
    extern __shared__ float sm[];
    __nv_bfloat16* Qs = (__nv_bfloat16*)sm;            // [32][264] bf16 Q
    __nv_bfloat16* Ks = Qs + 32 * 264;                 // [256][72] bf16 K slab
    float* Ss = (float*)((char*)sm + (32 * 264 + 256 * 72) * 2);  // [32][260] f32
    const unsigned* Qu = (const unsigned*)Qs;
    const unsigned* Ku = (const unsigned*)Ks;

    int tid = threadIdx.x;
    int lane = tid & 31, warp = tid >> 5;
    int g = lane >> 2, t = lane & 3;
    int b = blockIdx.x >> 6;
    int qtile = blockIdx.x & 63;
    const float* Qg = Qb + ((size_t)b * 2048 + qtile * 32) * 256;
    const float* Kg = Kf + (size_t)b * 8192 * 256;
    const __nv_bfloat16* Kbg = Kbf + (size_t)b * 8192 * 256;
    const float* Vg = Vf + (size_t)b * 8192 * 256;

    // stage Q tile as bf16 once
    for (int i = tid; i < 32 * 256; i += 256) {
        int q = i >> 8, d = i & 255;
        Qs[q * 264 + d] = __float2bfloat16(Qg[i]);
    }

    // approx top-64 per query: lane l holds ranks l (v0/i0) and 32+l (v1/i1)
    float v0[4], v1[4], thr[4];
    int i0[4], i1[4];
#pragma unroll
    for (int s = 0; s < 4; ++s) {
        v0[s] = -INFINITY; v1[s] = -INFINITY; thr[s] = -INFINITY;
        i0[s] = 0; i1[s] = 0;
    }

    int nb = 32 * warp;   // this warp's cell base within the chunk

    for (int chunk = 0; chunk < 32; ++chunk) {
        int cb = chunk * 256;
        float dacc[2][4][4];
#pragma unroll
        for (int mt = 0; mt < 2; ++mt)
#pragma unroll
            for (int ns = 0; ns < 4; ++ns)
#pragma unroll
                for (int r = 0; r < 4; ++r) dacc[mt][ns][r] = 0.f;

        for (int slab = 0; slab < 4; ++slab) {
            int kb = slab * 64;
            __syncthreads();
            // stage K slab: 256 cells x 64 dims bf16 (16B per ld/st)
#pragma unroll
            for (int pp = 0; pp < 8; ++pp) {
                int i = pp * 256 + tid;
                int c = i >> 3, seg = i & 7;
                float4 v = *(const float4*)(Kbg + (size_t)(cb + c) * 256 + kb + seg * 8);
                *(float4*)(Ks + c * 72 + seg * 8) = v;
            }
            __syncthreads();
#pragma unroll
            for (int kt = 0; kt < 4; ++kt) {
                int aw = kb / 2 + kt * 8 + t;   // word offset within Q row
                unsigned a[2][4];
#pragma unroll
                for (int mt = 0; mt < 2; ++mt) {
                    const unsigned* qr = Qu + (16 * mt + g) * 132;
                    a[mt][0] = qr[aw];
                    a[mt][1] = qr[8 * 132 + aw];
                    a[mt][2] = qr[aw + 4];
                    a[mt][3] = qr[8 * 132 + aw + 4];
                }
                int bw = kt * 8 + t;
#pragma unroll
                for (int ns = 0; ns < 4; ++ns) {
                    unsigned b0 = Ku[(nb + 8 * ns + g) * 36 + bw];
                    unsigned b1 = Ku[(nb + 8 * ns + g) * 36 + bw + 4];
                    mma_bf16(&dacc[0][ns][0], a[0], b0, b1);
                    mma_bf16(&dacc[1][ns][0], a[1], b0, b1);
                }
            }
        }

        // epilogue: accumulators -> Ss (scaled by 1/16)
#pragma unroll
        for (int mt = 0; mt < 2; ++mt)
#pragma unroll
            for (int ns = 0; ns < 4; ++ns) {
                int row = 16 * mt + g;
                int col = nb + 8 * ns + 2 * t;
                *(float2*)&Ss[row * 260 + col] =
                    make_float2(dacc[mt][ns][0] * 0.0625f, dacc[mt][ns][1] * 0.0625f);
                *(float2*)&Ss[(row + 8) * 260 + col] =
                    make_float2(dacc[mt][ns][2] * 0.0625f, dacc[mt][ns][3] * 0.0625f);
            }
        __syncthreads();

        // streaming approx top-64: warp w owns queries 4w..4w+3
#pragma unroll
        for (int sub = 0; sub < 4; ++sub) {
            int q = 4 * warp + sub;
#pragma unroll
            for (int r = 0; r < 8; ++r) {
                float s = Ss[q * 260 + r * 32 + lane];
                unsigned candm = __ballot_sync(FULL, s > thr[sub]);
                while (candm) {
                    int src = __ffs(candm) - 1;
                    candm &= candm - 1;
                    float v = __shfl_sync(FULL, s, src);
                    if (v > thr[sub]) {
                        int nidx = cb + r * 32 + src;
                        unsigned ge0 = __ballot_sync(FULL, v0[sub] >= v);
                        unsigned ge1 = __ballot_sync(FULL, v1[sub] >= v);
                        int p = __popc(ge0) + __popc(ge1);
                        float b31v = __shfl_sync(FULL, v0[sub], 31);
                        int   b31i = __shfl_sync(FULL, i0[sub], 31);
                        float v0u = __shfl_up_sync(FULL, v0[sub], 1);
                        int   i0u = __shfl_up_sync(FULL, i0[sub], 1);
                        float v1u = __shfl_up_sync(FULL, v1[sub], 1);
                        int   i1u = __shfl_up_sync(FULL, i1[sub], 1);
                        if (p < 32) {
                            if (lane > p)       { v0[sub] = v0u; i0[sub] = i0u; }
                            else if (lane == p) { v0[sub] = v;   i0[sub] = nidx; }
                            v1[sub] = (lane == 0) ? b31v : v1u;
                            i1[sub] = (lane == 0) ? b31i : i1u;
                        } else {
                            int pq = p - 32;
                            if (lane > pq)       { v1[sub] = v1u; i1[sub] = i1u; }
                            else if (lane == pq) { v1[sub] = v;   i1[sub] = nidx; }
                        }
                        thr[sub] = __shfl_sync(FULL, v1[sub], 31);
                    }
                }
            }
        }
    }

    // ---- exact fp32 rescore of 64 candidates (each lane owns 2 candidates,
    //      sequential ascending-k FFMA chain == reference-correlated order),
    //      then exact top-32 via strict total order + softmax + context ----
#pragma unroll
    for (int sub = 0; sub < 4; ++sub) {
        size_t row = (size_t)b * 2048 + qtile * 32 + 4 * warp + sub;
        const float* Qrow = Qg + (4 * warp + sub) * 256;
        const float* k0p = Kg + (size_t)i0[sub] * 256;
        const float* k1p = Kg + (size_t)i1[sub] * 256;

        float s0 = 0.f, s1 = 0.f;
#pragma unroll 8
        for (int dq = 0; dq < 64; ++dq) {
            float4 q4 = *(const float4*)&Qrow[4 * dq];   // broadcast across lanes
            float4 a4 = *(const float4*)&k0p[4 * dq];
            float4 b4 = *(const float4*)&k1p[4 * dq];
            s0 = fmaf(q4.x, a4.x, s0); s0 = fmaf(q4.y, a4.y, s0);
            s0 = fmaf(q4.z, a4.z, s0); s0 = fmaf(q4.w, a4.w, s0);
            s1 = fmaf(q4.x, b4.x, s1); s1 = fmaf(q4.y, b4.y, s1);
            s1 = fmaf(q4.z, b4.z, s1); s1 = fmaf(q4.w, b4.w, s1);
        }
        s0 *= 0.0625f;
        s1 *= 0.0625f;

        // exact top-32 among 64 candidates. Comparator (value desc, idx asc)
        // is a strict total order (indices distinct), so the result is
        // independent of insertion order and matches JAX top_k tie rules.
        float ev = -INFINITY;
        int ei = 0x7fffffff;
        for (int k = 0; k < 64; ++k) {
            float v  = (k < 32) ? __shfl_sync(FULL, s0, k)
                                : __shfl_sync(FULL, s1, k - 32);
            int cell = (k < 32) ? __shfl_sync(FULL, i0[sub], k)
                                : __shfl_sync(FULL, i1[sub], k - 32);
            unsigned ge = __ballot_sync(FULL, ev > v || (ev == v && ei < cell));
            int p = __popc(ge);
            float evu = __shfl_up_sync(FULL, ev, 1);
            int   eiu = __shfl_up_sync(FULL, ei, 1);
            if (lane > p)       { ev = evu; ei = eiu; }
            else if (lane == p) { ev = v;   ei = cell; }
        }

        // softmax over sorted-desc exact top-32
        float m = __shfl_sync(FULL, ev, 0);
        float e = expf(ev - m);
        float ssum = e;
#pragma unroll
        for (int o = 16; o; o >>= 1) ssum += __shfl_xor_sync(FULL, ssum, o);
        float w = e / ssum;
        out_attn[row * 32 + lane] = w;
        out_idx[row * 32 + lane] = (float)ei;

        // context = sum_k w_k * V[idx_k]
        float c[8];
#pragma unroll
        for (int j = 0; j < 8; ++j) c[j] = 0.f;
#pragma unroll
        for (int k = 0; k < 32; ++k) {
            float wk = __shfl_sync(FULL, w, k);
            int cell = __shfl_sync(FULL, ei, k);
            const float* vr = Vg + (size_t)cell * 256 + lane * 8;
            float4 va = *(const float4*)vr;
            float4 vb = *(const float4*)(vr + 4);
            c[0] += wk * va.x; c[1] += wk * va.y; c[2] += wk * va.z; c[3] += wk * va.w;
            c[4] += wk * vb.x; c[5] += wk * vb.y; c[6] += wk * vb.z; c[7] += wk * vb.w;
        }
        float* cp = ctx + row * 256 + lane * 8;
        *(float4*)cp       = make_float4(c[0], c[1], c[2], c[3]);
        *(float4*)(cp + 4) = make_float4(c[4], c[5], c[6], c[7]);
    }
}

// ---------------- launch ----------------
extern "C" void kernel_launch(void* const* d_in, const int* in_sizes, int n_in,
                              void* d_out, int out_size) {
    const float* micro = (const float*)d_in[0];
    const float* macro = (const float*)d_in[1];
    const float* mp_w  = (const float*)d_in[2];
    const float* mp_b  = (const float*)d_in[3];
    const float* wq    = (const float*)d_in[4];
    const float* wk    = (const float*)d_in[5];
    const float* wv    = (const float*)d_in[6];
    const float* op_w  = (const float*)d_in[7];
    const float* op_b  = (const float*)d_in[8];
    float* out = (float*)d_out;

    float *xm, *Qb, *Kf, *Vf, *ctx;
    __nv_bfloat16* Kbf;
    cudaGetSymbolAddress((void**)&xm,  g_xmicro);
    cudaGetSymbolAddress((void**)&Qb,  g_Q);
    cudaGetSymbolAddress((void**)&Kf,  g_K);
    cudaGetSymbolAddress((void**)&Vf,  g_V);
    cudaGetSymbolAddress((void**)&ctx, g_ctx);
    cudaGetSymbolAddress((void**)&Kbf, g_Kbf);

    micro_proj_kernel<<<8192, 256>>>(micro, mp_w, mp_b, xm);
    gemm256_kernel<<<dim3(64, 2), 256>>>(xm, wq, nullptr, nullptr, Qb, nullptr);
    gemm256_kernel<<<dim3(256, 2), 256>>>(macro, wk, nullptr, nullptr, Kf, Kbf);
    gemm256_kernel<<<dim3(256, 2), 256>>>(macro, wv, nullptr, nullptr, Vf, nullptr);

    int smem = (32 * 264 + 256 * 72) * 2 + 32 * 260 * 4;   // 87040 B
    cudaFuncSetAttribute(attn_topk_kernel,
                         cudaFuncAttributeMaxDynamicSharedMemorySize, smem);
    attn_topk_kernel<<<256, 256, smem>>>(Qb, Kf, Kbf, Vf, ctx,
                                         out + 8192 * 256,
                                         out + 8192 * 256 + 8192 * 32);

    gemm256_kernel<<<dim3(64, 2), 256>>>(ctx, op_w, op_b, xm, out, nullptr);
}